// round 1
// baseline (speedup 1.0000x reference)
#include <cuda_runtime.h>

// Problem constants
#define BB   8
#define CC   256
#define HH   96
#define WW   96
#define RR   64
#define HWSZ 9216      // 96*96
#define GG   16
#define GCH  16
#define KK   49

// Scratch for x = relu(bn(W1 @ guide)) : [B][R][H*W]
__device__ float g_x[BB * RR * HWSZ];

// ---------- packed f32x2 helpers (Blackwell sm_10x) ----------
__device__ __forceinline__ unsigned long long pack2(float lo, float hi) {
    unsigned long long r;
    asm("mov.b64 %0, {%1, %2};" : "=l"(r) : "f"(lo), "f"(hi));
    return r;
}
__device__ __forceinline__ void unpack2(unsigned long long v, float& lo, float& hi) {
    asm("mov.b64 {%0, %1}, %2;" : "=f"(lo), "=f"(hi) : "l"(v));
}
__device__ __forceinline__ void fma2(unsigned long long& d,
                                     unsigned long long a,
                                     unsigned long long b) {
    asm("fma.rn.f32x2 %0, %1, %2, %0;" : "+l"(d) : "l"(a), "l"(b));
}

// =====================================================================
// Kernel 1: x[b,r,p] = relu( a[r] * (W1[r,:] . guide[b,:,p]) + c[r] )
// GEMM M=64, N=256 pixels/block, K=256. f32x2 packs pixel pairs
// (weight splat). W1 fully resident in smem; guide staged in 32-k chunks.
// =====================================================================
__global__ void __launch_bounds__(256, 2)
k1_gemm_bn_relu(const float* __restrict__ guide, const float* __restrict__ W1,
                const float* __restrict__ gamma_, const float* __restrict__ beta_,
                const float* __restrict__ mean_, const float* __restrict__ var_)
{
    extern __shared__ float sm1[];
    float* Ws = sm1;               // [64][256]
    float* Gs = sm1 + 64 * 256;    // [32][256]

    const int tid = threadIdx.x;
    const int b   = blockIdx.y;
    const int p0  = blockIdx.x * 256;

    for (int i = tid; i < 64 * 256; i += 256) Ws[i] = W1[i];

    unsigned long long acc[8][4];
#pragma unroll
    for (int i = 0; i < 8; ++i)
#pragma unroll
        for (int j = 0; j < 4; ++j) acc[i][j] = 0ull;

    const int pc = tid & 31;   // pixel-pair column
    const int rg = tid >> 5;   // r row-group (8 rows each)
    const float* gb = guide + (size_t)b * CC * HWSZ + p0;

    for (int kc = 0; kc < 256; kc += 32) {
        __syncthreads();
#pragma unroll
        for (int i = 0; i < 32; ++i) {
            int ldx = tid + i * 256;
            int k = ldx >> 8, p = ldx & 255;
            Gs[ldx] = gb[(kc + k) * HWSZ + p];
        }
        __syncthreads();
#pragma unroll 4
        for (int k = 0; k < 32; ++k) {
            unsigned long long wq[8], gv[4];
#pragma unroll
            for (int i = 0; i < 8; ++i) {
                float w = Ws[(rg * 8 + i) * 256 + kc + k];
                wq[i] = pack2(w, w);
            }
#pragma unroll
            for (int j = 0; j < 4; ++j)
                gv[j] = *(const unsigned long long*)(Gs + k * 256 + 2 * (pc + 32 * j));
#pragma unroll
            for (int i = 0; i < 8; ++i)
#pragma unroll
                for (int j = 0; j < 4; ++j) fma2(acc[i][j], wq[i], gv[j]);
        }
    }

#pragma unroll
    for (int i = 0; i < 8; ++i) {
        int r = rg * 8 + i;
        float a = gamma_[r] * rsqrtf(var_[r] + 1e-5f);
        float c = beta_[r] - mean_[r] * a;
        float* xb = g_x + ((size_t)b * RR + r) * HWSZ + p0;
#pragma unroll
        for (int j = 0; j < 4; ++j) {
            float lo, hi;
            unpack2(acc[i][j], lo, hi);
            float2 y;
            y.x = fmaxf(fmaf(a, lo, c), 0.0f);
            y.y = fmaxf(fmaf(a, hi, c), 0.0f);
            *(float2*)(xb + 2 * (pc + 32 * j)) = y;
        }
    }
}

// =====================================================================
// Kernel 2 (fused): per (b, 16x16 pixel tile), loop g in [0,16):
//   dfs[49][256] = W2_g[49][64] @ xs[64][256]     (f32x2 over K pairs)
//   out[g,:,tile] = sum_idx fm_patch * dfs + fm   (f32x2 over gc pairs)
// smem: xs[256][66] transposed (K-contiguous), dfs[49][256],
//       union{ w2s[64][66] , fm patch [22*22][20] (pad-20: 16B-aligned,
//              conflict-free LDS.128) }
// =====================================================================
#define XS_FLT   (256 * 66)
#define DFS_FLT  (49 * 256)
#define SHP_FLT  (484 * 20)            // >= 64*66
#define K2_SMEM  ((XS_FLT + DFS_FLT + SHP_FLT) * 4)

__global__ void __launch_bounds__(512, 1)
k2_fused(const float* __restrict__ fm, const float* __restrict__ W2,
         float* __restrict__ out)
{
    extern __shared__ float sm2[];
    float* xs  = sm2;                        // [256][66]  x transposed
    float* dfs = sm2 + XS_FLT;               // [49][256]
    float* shp = sm2 + XS_FLT + DFS_FLT;     // union w2s / fm patch

    const int tid  = threadIdx.x;
    const int b    = blockIdx.y;
    const int tile = blockIdx.x;
    const int ti0  = (tile / 6) * 16;
    const int tj0  = (tile % 6) * 16;

    // load xs transposed: xs[p][k] = x[b][k][pixel(p)]
#pragma unroll
    for (int i = 0; i < 32; ++i) {           // 64*256/512
        int ldx = tid + i * 512;
        int k = ldx >> 8, p = ldx & 255;
        int gi = ti0 + (p >> 4), gj = tj0 + (p & 15);
        xs[p * 66 + k] = g_x[((size_t)b * RR + k) * HWSZ + gi * WW + gj];
    }

    const float* fmb  = fm  + (size_t)b * CC * HWSZ;
    float*       outb = out + (size_t)b * CC * HWSZ;

    const int pc = tid & 63;      // GEMM pixel column
    const int rg = tid >> 6;      // GEMM row group (8 rows)
    const int p  = tid & 255;     // involution pixel
    const int gh = tid >> 8;      // involution gc-half (0/1)
    const int ti = p >> 4, tj = p & 15;

    for (int g = 0; g < 16; ++g) {
        __syncthreads();   // prev inv done reading shp/dfs
        // --- stage W2 slice for group g (rows padded to 64 with zeros) ---
        for (int i = tid; i < 64 * 64; i += 512) {
            int row = i >> 6, c = i & 63;
            shp[row * 66 + c] = (row < 49) ? W2[(g * 49 + row) * 64 + c] : 0.0f;
        }
        __syncthreads();

        // --- df GEMM: M=64(pad) x N=256 x K=64, K packed in f32x2 pairs ---
        {
            unsigned long long acc[8][4];
#pragma unroll
            for (int i = 0; i < 8; ++i)
#pragma unroll
                for (int j = 0; j < 4; ++j) acc[i][j] = 0ull;

#pragma unroll 4
            for (int kp = 0; kp < 32; ++kp) {
                unsigned long long av[8], bv[4];
#pragma unroll
                for (int i = 0; i < 8; ++i)
                    av[i] = *(const unsigned long long*)(shp + (rg * 8 + i) * 66 + 2 * kp);
#pragma unroll
                for (int j = 0; j < 4; ++j)
                    bv[j] = *(const unsigned long long*)(xs + (pc + 64 * j) * 66 + 2 * kp);
#pragma unroll
                for (int i = 0; i < 8; ++i)
#pragma unroll
                    for (int j = 0; j < 4; ++j) fma2(acc[i][j], av[i], bv[j]);
            }
#pragma unroll
            for (int i = 0; i < 8; ++i) {
                int row = rg * 8 + i;
                if (row < 49) {
#pragma unroll
                    for (int j = 0; j < 4; ++j) {
                        float lo, hi;
                        unpack2(acc[i][j], lo, hi);
                        dfs[row * 256 + pc + 64 * j] = lo + hi;
                    }
                }
            }
        }
        __syncthreads();   // dfs ready; w2s reads done -> shp reusable

        // --- stage fm patch [22][22][16gc], pad-20, zero OOB ---
        for (int i = tid; i < 484 * 16; i += 512) {
            int ii  = i / 352;            // 22*16
            int rem = i - ii * 352;
            int gc  = rem / 22;
            int jj  = rem - gc * 22;
            int gi = ti0 - 3 + ii, gj = tj0 - 3 + jj;
            float v = 0.0f;
            if ((unsigned)gi < 96u && (unsigned)gj < 96u)
                v = fmb[(g * 16 + gc) * HWSZ + gi * WW + gj];
            shp[(ii * 22 + jj) * 20 + gc] = v;
        }
        __syncthreads();

        // --- involution + residual: 2 threads/pixel, 8 gc each (f32x2) ---
        {
            unsigned long long a2[4] = {0ull, 0ull, 0ull, 0ull};
#pragma unroll
            for (int idx = 0; idx < 49; ++idx) {
                const int di = idx / 7, dj = idx - di * 7;
                float dfv = dfs[idx * 256 + p];
                unsigned long long dq = pack2(dfv, dfv);
                const ulonglong2* f4 = (const ulonglong2*)(shp +
                    ((ti + di) * 22 + (tj + dj)) * 20 + gh * 8);
                ulonglong2 u0 = f4[0];
                ulonglong2 u1 = f4[1];
                fma2(a2[0], u0.x, dq);
                fma2(a2[1], u0.y, dq);
                fma2(a2[2], u1.x, dq);
                fma2(a2[3], u1.y, dq);
            }
            const float* fc = shp + ((ti + 3) * 22 + (tj + 3)) * 20 + gh * 8;
            float* op = outb + (size_t)(g * 16 + gh * 8) * HWSZ
                             + (ti0 + ti) * WW + (tj0 + tj);
#pragma unroll
            for (int q = 0; q < 4; ++q) {
                float lo, hi;
                unpack2(a2[q], lo, hi);
                op[(size_t)(2 * q)     * HWSZ] = lo + fc[2 * q];
                op[(size_t)(2 * q + 1) * HWSZ] = hi + fc[2 * q + 1];
            }
        }
    }
}

// =====================================================================
extern "C" void kernel_launch(void* const* d_in, const int* in_sizes, int n_in,
                              void* d_out, int out_size)
{
    (void)in_sizes; (void)n_in; (void)out_size;
    const float* fm    = (const float*)d_in[0];
    const float* guide = (const float*)d_in[1];
    const float* W1    = (const float*)d_in[2];
    const float* gma   = (const float*)d_in[3];
    const float* bta   = (const float*)d_in[4];
    const float* mu    = (const float*)d_in[5];
    const float* var   = (const float*)d_in[6];
    const float* W2    = (const float*)d_in[7];
    float* out = (float*)d_out;

    const int k1_smem = (64 * 256 + 32 * 256) * 4;   // 96 KB
    cudaFuncSetAttribute(k1_gemm_bn_relu,
                         cudaFuncAttributeMaxDynamicSharedMemorySize, k1_smem);
    cudaFuncSetAttribute(k2_fused,
                         cudaFuncAttributeMaxDynamicSharedMemorySize, K2_SMEM);

    dim3 grid(36, 8);
    k1_gemm_bn_relu<<<grid, 256, k1_smem>>>(guide, W1, gma, bta, mu, var);
    k2_fused<<<grid, 512, K2_SMEM>>>(fm, W2, out);
}

// round 2
// speedup vs baseline: 1.2937x; 1.2937x over previous
#include <cuda_runtime.h>
#include <cstdint>

#define BB   8
#define CC   256
#define HH   96
#define WW   96
#define RR   64
#define HWSZ 9216
#define GG   16
#define KK   49

__device__ float g_x[BB * RR * HWSZ];

typedef unsigned long long u64;

// ---------- packed f32x2 helpers (Blackwell sm_10x) ----------
__device__ __forceinline__ u64 pack2(float lo, float hi) {
    u64 r;
    asm("mov.b64 %0, {%1, %2};" : "=l"(r) : "f"(lo), "f"(hi));
    return r;
}
__device__ __forceinline__ void unpack2(u64 v, float& lo, float& hi) {
    asm("mov.b64 {%0, %1}, %2;" : "=f"(lo), "=f"(hi) : "l"(v));
}
__device__ __forceinline__ void fma2(u64& d, u64 a, u64 b) {
    asm("fma.rn.f32x2 %0, %1, %2, %0;" : "+l"(d) : "l"(a), "l"(b));
}

// ---------- cp.async helpers ----------
__device__ __forceinline__ unsigned s2u(const void* p) {
    return (unsigned)__cvta_generic_to_shared(p);
}
__device__ __forceinline__ void cp16(void* dst, const void* src) {
    asm volatile("cp.async.cg.shared.global [%0], [%1], 16;\n"
                 :: "r"(s2u(dst)), "l"(src));
}
__device__ __forceinline__ void cp4z(void* dst, const void* src, bool pred) {
    int sz = pred ? 4 : 0;
    asm volatile("cp.async.ca.shared.global [%0], [%1], 4, %2;\n"
                 :: "r"(s2u(dst)), "l"(src), "r"(sz));
}
__device__ __forceinline__ void cp_commit() {
    asm volatile("cp.async.commit_group;\n" ::);
}
template<int N> __device__ __forceinline__ void cp_wait() {
    asm volatile("cp.async.wait_group %0;\n" :: "n"(N));
}

// =====================================================================
// Kernel 1: x[b,r,p] = relu(a[r]*(W1[r,:].guide[b,:,p]) + c[r])
// N-packed f32x2 GEMM M=64 x N=256px x K=256, cp.async double-buffered
// guide chunks (16 k per chunk).
// =====================================================================
#define K1_WS 16384          // 64*256
#define K1_GS 4096           // 16*256
#define K1_SMEM ((K1_WS + 2 * K1_GS) * 4)   // 96 KB -> 2 CTAs/SM

__global__ void __launch_bounds__(256, 2)
k1_gemm_bn_relu(const float* __restrict__ guide, const float* __restrict__ W1,
                const float* __restrict__ gamma_, const float* __restrict__ beta_,
                const float* __restrict__ mean_, const float* __restrict__ var_)
{
    extern __shared__ float sm1[];
    float* Ws = sm1;             // [64][256]
    float* Gs = sm1 + K1_WS;     // 2 x [16][256]

    const int tid = threadIdx.x;
    const int b   = blockIdx.y;
    const int p0  = blockIdx.x * 256;
    const float* gb = guide + (size_t)b * CC * HWSZ + p0;

    // prefetch W1 (whole) + guide chunk 0   -> group 0
    for (int i = tid; i < 4096; i += 256)
        cp16(Ws + i * 4, W1 + i * 4);
    for (int i = tid; i < 1024; i += 256) {
        int kr = i >> 6, c4 = i & 63;
        cp16(Gs + kr * 256 + c4 * 4, gb + kr * HWSZ + c4 * 4);
    }
    cp_commit();

    u64 acc[8][4];
#pragma unroll
    for (int i = 0; i < 8; ++i)
#pragma unroll
        for (int j = 0; j < 4; ++j) acc[i][j] = 0ull;

    const int pc = tid & 31;
    const int rg = tid >> 5;     // constant within a warp -> broadcast W loads

    for (int kc = 0; kc < 16; ++kc) {
        if (kc < 15) {
            float* dst = Gs + ((kc + 1) & 1) * K1_GS;
            const float* src = gb + (size_t)(kc + 1) * 16 * HWSZ;
            for (int i = tid; i < 1024; i += 256) {
                int kr = i >> 6, c4 = i & 63;
                cp16(dst + kr * 256 + c4 * 4, src + kr * HWSZ + c4 * 4);
            }
            cp_commit();
            cp_wait<1>();
        } else {
            cp_wait<0>();
        }
        __syncthreads();

        const float* G  = Gs + (kc & 1) * K1_GS;
        const float* Wr = Ws + (rg * 8) * 256 + kc * 16;
#pragma unroll
        for (int kk = 0; kk < 16; kk += 4) {
            float4 wv[8];
#pragma unroll
            for (int i = 0; i < 8; ++i)
                wv[i] = *(const float4*)(Wr + i * 256 + kk);
#pragma unroll
            for (int t = 0; t < 4; ++t) {
                u64 bv[4];
#pragma unroll
                for (int j = 0; j < 4; ++j)
                    bv[j] = *(const u64*)(G + (kk + t) * 256 + 2 * (pc + 32 * j));
#pragma unroll
                for (int i = 0; i < 8; ++i) {
                    float w = (&wv[i].x)[t];
                    u64 wq = pack2(w, w);
#pragma unroll
                    for (int j = 0; j < 4; ++j) fma2(acc[i][j], wq, bv[j]);
                }
            }
        }
        __syncthreads();
    }

#pragma unroll
    for (int i = 0; i < 8; ++i) {
        int r = rg * 8 + i;
        float a = gamma_[r] * rsqrtf(var_[r] + 1e-5f);
        float c = beta_[r] - mean_[r] * a;
        float* xb = g_x + ((size_t)b * RR + r) * HWSZ + p0;
#pragma unroll
        for (int j = 0; j < 4; ++j) {
            float lo, hi;
            unpack2(acc[i][j], lo, hi);
            float2 y;
            y.x = fmaxf(fmaf(a, lo, c), 0.0f);
            y.y = fmaxf(fmaf(a, hi, c), 0.0f);
            *(float2*)(xb + 2 * (pc + 32 * j)) = y;
        }
    }
}

// =====================================================================
// Kernel 2 (fused, pipelined): per (b, 16x16 tile), loop g:
//   prefetch(g+1) via cp.async  ||  dfs = W2_g @ xs (N-packed f32x2)
//   barrier; involution + residual; barrier.
// smem (floats):
//   xs   [64][256]            @ 0       (k-major)
//   dfs  [49][256]            @ 16384
//   w2b  2 x [49*64]          @ 28928
//   fmb  2 x [484*20]         @ 35200   (22x22 patch, pad-20, 16 gc)
// =====================================================================
#define XS_OFF   0
#define DFS_OFF  16384
#define W2_OFF   28928
#define W2_SZ    3136            // 49*64
#define FM_OFF   35200
#define FM_SZ    9680            // 484*20
#define K2_SMEM  ((FM_OFF + 2 * FM_SZ) * 4)   // 218240 B

__global__ void __launch_bounds__(512, 1)
k2_fused(const float* __restrict__ fm, const float* __restrict__ W2,
         float* __restrict__ out)
{
    extern __shared__ float sm2[];
    float* xs  = sm2 + XS_OFF;
    float* dfs = sm2 + DFS_OFF;
    float* w2b = sm2 + W2_OFF;
    float* fmb = sm2 + FM_OFF;

    const int tid  = threadIdx.x;
    const int b    = blockIdx.y;
    const int tile = blockIdx.x;
    const int ti0  = (tile / 6) * 16;
    const int tj0  = (tile % 6) * 16;

    const float* fmbase = fm + (size_t)b * CC * HWSZ;
    float*       outb   = out + (size_t)b * CC * HWSZ;

    // ---- prefetch g=0: W2 slice + fm patch into buffer 0 ----
    {
        for (int i = tid; i < 784; i += 512)            // 49*64/4 float4
            cp16(w2b + i * 4, W2 + i * 4);
        for (int i = tid; i < 484 * 16; i += 512) {
            int ii  = i / 352;
            int rem = i - ii * 352;
            int gc  = rem / 22;
            int jj  = rem - gc * 22;
            int gi = ti0 - 3 + ii, gj = tj0 - 3 + jj;
            bool ok = ((unsigned)gi < 96u) && ((unsigned)gj < 96u);
            int gic = ok ? gi : 0, gjc = ok ? gj : 0;
            cp4z(fmb + (ii * 22 + jj) * 20 + gc,
                 fmbase + (size_t)gc * HWSZ + gic * WW + gjc, ok);
        }
        cp_commit();
    }

    // ---- load xs k-major: xs[k][p] = x[b][k][pixel(p)] ----
#pragma unroll
    for (int i = 0; i < 32; ++i) {
        int ldx = tid + i * 512;
        int k = ldx >> 8, p = ldx & 255;
        int gi = ti0 + (p >> 4), gj = tj0 + (p & 15);
        xs[k * 256 + p] = g_x[((size_t)b * RR + k) * HWSZ + gi * WW + gj];
    }

    cp_wait<0>();
    __syncthreads();

    const int pc = tid & 63;       // GEMM pixel-pair column (pairs pc, pc+64)
    const int rg = tid >> 6;       // GEMM row group (7 rows), rg==7 idle
    const int p  = tid & 255;      // involution pixel
    const int gh = tid >> 8;       // involution gc-half
    const int ti = p >> 4, tj = p & 15;

    int cur = 0;
    for (int g = 0; g < 16; ++g) {
        // ---- prefetch g+1 into other buffer (overlaps GEMM) ----
        if (g < 15) {
            float* w2d = w2b + (cur ^ 1) * W2_SZ;
            float* fmd = fmb + (cur ^ 1) * FM_SZ;
            const float* w2s = W2 + (size_t)(g + 1) * W2_SZ;
            const float* fms = fmbase + (size_t)(g + 1) * 16 * HWSZ;
            for (int i = tid; i < 784; i += 512)
                cp16(w2d + i * 4, w2s + i * 4);
            for (int i = tid; i < 484 * 16; i += 512) {
                int ii  = i / 352;
                int rem = i - ii * 352;
                int gc  = rem / 22;
                int jj  = rem - gc * 22;
                int gi = ti0 - 3 + ii, gj = tj0 - 3 + jj;
                bool ok = ((unsigned)gi < 96u) && ((unsigned)gj < 96u);
                int gic = ok ? gi : 0, gjc = ok ? gj : 0;
                cp4z(fmd + (ii * 22 + jj) * 20 + gc,
                     fms + (size_t)gc * HWSZ + gic * WW + gjc, ok);
            }
            cp_commit();
        }

        // ---- df GEMM: 49 x 256px x 64, N-packed f32x2, w-splat ----
        if (rg < 7) {
            const float* w2c = w2b + cur * W2_SZ + (rg * 7) * 64;
            u64 acc[7][2];
#pragma unroll
            for (int i = 0; i < 7; ++i) { acc[i][0] = 0ull; acc[i][1] = 0ull; }

#pragma unroll 4
            for (int kk = 0; kk < 64; kk += 4) {
                float4 wv[7];
#pragma unroll
                for (int i = 0; i < 7; ++i)
                    wv[i] = *(const float4*)(w2c + i * 64 + kk);
#pragma unroll
                for (int t = 0; t < 4; ++t) {
                    u64 b0 = *(const u64*)(xs + (kk + t) * 256 + 2 * pc);
                    u64 b1 = *(const u64*)(xs + (kk + t) * 256 + 2 * pc + 128);
#pragma unroll
                    for (int i = 0; i < 7; ++i) {
                        float w = (&wv[i].x)[t];
                        u64 wq = pack2(w, w);
                        fma2(acc[i][0], wq, b0);
                        fma2(acc[i][1], wq, b1);
                    }
                }
            }
#pragma unroll
            for (int i = 0; i < 7; ++i) {
                int row = rg * 7 + i;
                float lo, hi;
                unpack2(acc[i][0], lo, hi);
                *(float2*)(dfs + row * 256 + 2 * pc) = make_float2(lo, hi);
                unpack2(acc[i][1], lo, hi);
                *(float2*)(dfs + row * 256 + 2 * pc + 128) = make_float2(lo, hi);
            }
        }
        __syncthreads();   // dfs visible

        // ---- involution + residual ----
        {
            const float* fmc = fmb + cur * FM_SZ;
            u64 a2[4] = {0ull, 0ull, 0ull, 0ull};
#pragma unroll
            for (int idx = 0; idx < 49; ++idx) {
                const int di = idx / 7, dj = idx - di * 7;
                float dfv = dfs[idx * 256 + p];
                u64 dq = pack2(dfv, dfv);
                const ulonglong2* f4 = (const ulonglong2*)(fmc +
                    ((ti + di) * 22 + (tj + dj)) * 20 + gh * 8);
                ulonglong2 u0 = f4[0];
                ulonglong2 u1 = f4[1];
                fma2(a2[0], u0.x, dq);
                fma2(a2[1], u0.y, dq);
                fma2(a2[2], u1.x, dq);
                fma2(a2[3], u1.y, dq);
            }
            const float* fc = fmc + ((ti + 3) * 22 + (tj + 3)) * 20 + gh * 8;
            float* op = outb + (size_t)(g * 16 + gh * 8) * HWSZ
                             + (ti0 + ti) * WW + (tj0 + tj);
#pragma unroll
            for (int q = 0; q < 4; ++q) {
                float lo, hi;
                unpack2(a2[q], lo, hi);
                op[(size_t)(2 * q)     * HWSZ] = lo + fc[2 * q];
                op[(size_t)(2 * q + 1) * HWSZ] = hi + fc[2 * q + 1];
            }
        }

        cp_wait<0>();      // prefetch landed
        __syncthreads();   // safe to overwrite dfs / swap buffers
        cur ^= 1;
    }
}

// =====================================================================
extern "C" void kernel_launch(void* const* d_in, const int* in_sizes, int n_in,
                              void* d_out, int out_size)
{
    (void)in_sizes; (void)n_in; (void)out_size;
    const float* fm    = (const float*)d_in[0];
    const float* guide = (const float*)d_in[1];
    const float* W1    = (const float*)d_in[2];
    const float* gma   = (const float*)d_in[3];
    const float* bta   = (const float*)d_in[4];
    const float* mu    = (const float*)d_in[5];
    const float* var   = (const float*)d_in[6];
    const float* W2    = (const float*)d_in[7];
    float* out = (float*)d_out;

    cudaFuncSetAttribute(k1_gemm_bn_relu,
                         cudaFuncAttributeMaxDynamicSharedMemorySize, K1_SMEM);
    cudaFuncSetAttribute(k2_fused,
                         cudaFuncAttributeMaxDynamicSharedMemorySize, K2_SMEM);

    dim3 grid(36, 8);
    k1_gemm_bn_relu<<<grid, 256, K1_SMEM>>>(guide, W1, gma, bta, mu, var);
    k2_fused<<<grid, 512, K2_SMEM>>>(fm, W2, out);
}